// round 11
// baseline (speedup 1.0000x reference)
#include <cuda_runtime.h>

// Fully fused shift + H-conv(128->8 via w1) + W-conv(8->128 via w2), (1,128,56,56) fp32.
// v9: grid (2,56) = 112 blocks x 1024 threads (1/SM, single wave). Chains halved vs v8:
//   phase1: 3 LDG.128 + 48 FMA (1 i/thread), masks folded into staged weights,
//   shfl_xor(16) i-pair pre-reduction, phase2: 1 float4 quad/thread.
//
// Stage 1: inter[k4][o][n] = sum_{i<64,j<3} w1[k4,i,j] * X(2i+o, m+j-1, n)
//   X(c,h,n) = x[c][(h-1+56)%56][n] if 0<=h<56 else 0  (roll(+1) in H, zero-pad H)
// Stage 2: out[i32*4+k4][m][n] = sum_{o,kk} w2[i32,o,kk] * inter[k4][o][n+kk-1]  (zero-pad W)

#define HH 56
#define WW 56
#define NF4B 8            // float4 columns per block (32 cols incl. halo)
#define TNO 28            // output cols per block
#define THREADS 1024      // 128 go-groups x 8 f4-columns

__global__ __launch_bounds__(THREADS)
void fused_shift_conv_v9(const float* __restrict__ x,
                         const float* __restrict__ w1,
                         const float* __restrict__ w2,
                         float* __restrict__ out)
{
    __shared__ float w1s[768];               // [k4][i64][j3], H-masks pre-folded
    __shared__ float w2s[192];               // [i32][o2][kk3]
    __shared__ float psum[256 * 32];         // [(gr*2+o)*4+k][local col]  32 KB
    __shared__ float inter_s[8 * 34];        // [o*4+k][local col + 1], idx 0 & 33 = zero halo

    const int tid = threadIdx.x;
    const int h   = blockIdx.x;              // 0..1 (n-half)
    const int m   = blockIdx.y;              // 0..55
    const int s4  = h * 6;                   // first global float4 col (0 or 6)
    const int nb  = h * TNO;                 // first output col (0 or 28)
    const int lshift = h * 4;                // local col = n2 + lshift

    const int f4l = tid & (NF4B - 1);        // local float4 col 0..7
    const int go  = tid >> 3;                // 0..127 = i*2 + o
    const int o   = go & 1;
    const int i   = go >> 1;                 // 0..63

    // H taps: rolled source rows + validity masks (uniform per block)
    float msk[3];
    int   h14[3];
    #pragma unroll
    for (int j = 0; j < 3; ++j) {
        const int hh = m + j - 1;                     // pre-roll coordinate
        msk[j] = (hh >= 0 && hh < HH) ? 1.f : 0.f;
        h14[j] = ((hh + 55) % HH) * 14;               // rolled row offset, float4 units
    }

    // ---- prefetch x: 3 independent LDG.128 (overlaps the weight staging) ----
    const float4* __restrict__ x4 = (const float4*)x;
    float4 xv[3];
    {
        const int c = 2 * i + o;
        const float4* xb = x4 + c * (HH * 14) + s4 + f4l;
        #pragma unroll
        for (int j = 0; j < 3; ++j)
            xv[j] = __ldg(xb + h14[j]);
    }

    // ---- stage weights to smem with H-masks folded in ----
    if (tid < 768) w1s[tid] = w1[tid] * msk[tid % 3];
    else if (tid < 960) w2s[tid - 768] = w2[tid - 768];
    __syncthreads();

    // ---------------- Phase 1: 48 FMAs from registers ----------------
    float4 acc[4];
    #pragma unroll
    for (int k = 0; k < 4; ++k) acc[k] = make_float4(0.f, 0.f, 0.f, 0.f);

    {
        const float* wb = w1s + i * 3;
        #pragma unroll
        for (int j = 0; j < 3; ++j) {
            const float4 v = xv[j];
            #pragma unroll
            for (int k = 0; k < 4; ++k) {
                const float w = wb[k * 192 + j];
                acc[k].x = fmaf(w, v.x, acc[k].x);
                acc[k].y = fmaf(w, v.y, acc[k].y);
                acc[k].z = fmaf(w, v.z, acc[k].z);
                acc[k].w = fmaf(w, v.w, acc[k].w);
            }
        }
    }

    // ---- shfl pre-reduction: combine i-pairs (i ^ 1), same o, same f4l ----
    // (go differs by 2 -> tid differs by 16 -> same warp)
    #pragma unroll
    for (int k = 0; k < 4; ++k) {
        acc[k].x += __shfl_xor_sync(0xffffffffu, acc[k].x, 16);
        acc[k].y += __shfl_xor_sync(0xffffffffu, acc[k].y, 16);
        acc[k].z += __shfl_xor_sync(0xffffffffu, acc[k].z, 16);
        acc[k].w += __shfl_xor_sync(0xffffffffu, acc[k].w, 16);
    }
    if (((tid >> 4) & 1) == 0) {             // i even: store the pair sum
        const int gr = i >> 1;               // reduced group 0..31
        float4* ps4 = (float4*)psum;
        #pragma unroll
        for (int k = 0; k < 4; ++k)
            ps4[((gr * 2 + o) * 4 + k) * NF4B + f4l] = acc[k];
    }
    __syncthreads();

    // ---- reduce 32 groups per (o,k,local col): 256 threads, one output each ----
    if (tid < 256) {
        const int ll = tid & 31;             // local col 0..31
        const int ok = tid >> 5;             // o*4 + k
        const int oo = ok >> 2;
        const int k  = ok & 3;
        float ssum = 0.f;
        #pragma unroll
        for (int g = 0; g < 32; ++g)
            ssum += psum[((g * 2 + oo) * 4 + k) * 32 + ll];
        inter_s[ok * 34 + ll + 1] = ssum;
        if (tid < 16)                        // zero halo at padded idx 0 and 33
            inter_s[(tid >> 1) * 34 + (tid & 1) * 33] = 0.f;
    }
    __syncthreads();

    // ---------------- Phase 2: 896 float4 quads, 1 per thread ----------------
    if (tid < 896) {
        const int f4o = tid % 7;             // output quad within half-row
        const int co  = tid / 7;             // 0..127 = i32*4 + k4
        const int i32 = co >> 2;
        const int k4  = co & 3;
        const int n0  = f4o * 4;             // output col base within half-row

        const float* wb = w2s + i32 * 6;
        float4 a = make_float4(0.f, 0.f, 0.f, 0.f);
        #pragma unroll
        for (int oo = 0; oo < 2; ++oo) {
            const float* ib = inter_s + (oo * 4 + k4) * 34 + n0 + lshift;  // taps +0..+5
            const float s0 = ib[0], s1 = ib[1], s2 = ib[2],
                        s3 = ib[3], s4v = ib[4], s5 = ib[5];
            const float wA = wb[oo * 3 + 0];
            const float wB = wb[oo * 3 + 1];
            const float wC = wb[oo * 3 + 2];
            a.x = fmaf(wA, s0, fmaf(wB, s1, fmaf(wC, s2, a.x)));
            a.y = fmaf(wA, s1, fmaf(wB, s2, fmaf(wC, s3, a.y)));
            a.z = fmaf(wA, s2, fmaf(wB, s3, fmaf(wC, s4v, a.z)));
            a.w = fmaf(wA, s3, fmaf(wB, s4v, fmaf(wC, s5, a.w)));
        }
        float4* __restrict__ out4 = (float4*)out;
        out4[(co * (HH * WW) + m * WW + nb + n0) >> 2] = a;
    }
}

extern "C" void kernel_launch(void* const* d_in, const int* in_sizes, int n_in,
                              void* d_out, int out_size)
{
    const float* x  = (const float*)d_in[0];   // (1,128,56,56)
    const float* w1 = (const float*)d_in[1];   // (4,64,3)
    const float* w2 = (const float*)d_in[2];   // (32,2,3)
    float* out = (float*)d_out;                // (1,128,56,56)

    dim3 grid(2, HH);                          // 112 blocks
    fused_shift_conv_v9<<<grid, THREADS>>>(x, w1, w2, out);
}

// round 12
// speedup vs baseline: 1.2361x; 1.2361x over previous
#include <cuda_runtime.h>

// Fully fused shift + H-conv(128->8 via w1) + W-conv(8->128 via w2), (1,128,56,56) fp32.
// v10 = v8 + (a) H-masks folded into staged w1 (kills 24 FMUL/thread pre-barrier),
//            (b) shfl_xor(16) i-pair pre-reduction (psum 32->16KB, reduce loop 32->16).
// Grid (2,56) = 112 blocks x 512 threads (1/SM, single wave).
//
// Stage 1: inter[k4][o][n] = sum_{i<64,j<3} w1[k4,i,j] * X(2i+o, m+j-1, n)
//   X(c,h,n) = x[c][(h-1+56)%56][n] if 0<=h<56 else 0  (roll(+1) in H, zero-pad H)
// Stage 2: out[i32*4+k4][m][n] = sum_{o,kk} w2[i32,o,kk] * inter[k4][o][n+kk-1]  (zero-pad W)

#define HH 56
#define WW 56
#define NF4B 8            // float4 columns per block (32 cols incl. halo)
#define TNO 28            // output cols per block
#define THREADS 512       // 64 go-groups x 8 f4-columns

__global__ __launch_bounds__(THREADS)
void fused_shift_conv_v10(const float* __restrict__ x,
                          const float* __restrict__ w1,
                          const float* __restrict__ w2,
                          float* __restrict__ out)
{
    __shared__ float w1s[768];               // [k4][i64][j3], H-masks pre-folded
    __shared__ float w2s[192];               // [i32][o2][kk3]
    __shared__ float psum[128 * 32];         // [(gr*2+o)*4+k][local col]  16 KB
    __shared__ float inter_s[8 * 34];        // [o*4+k][local col + 1], idx 0 & 33 = zero halo

    const int tid = threadIdx.x;
    const int h   = blockIdx.x;              // 0..1 (n-half)
    const int m   = blockIdx.y;              // 0..55
    const int s4  = h * 6;                   // first global float4 col (0 or 6)
    const int nb  = h * TNO;                 // first output col (0 or 28)
    const int lshift = h * 4;                // local col = n2 + lshift

    const int f4l = tid & (NF4B - 1);        // local float4 col 0..7
    const int go  = tid >> 3;                // 0..63 = ig*2 + o
    const int o   = go & 1;
    const int ig  = go >> 1;                 // 0..31, 2 i-values each

    // H taps: rolled source rows + validity masks (uniform per block)
    float msk[3];
    int   h14[3];
    #pragma unroll
    for (int j = 0; j < 3; ++j) {
        const int hh = m + j - 1;                     // pre-roll coordinate
        msk[j] = (hh >= 0 && hh < HH) ? 1.f : 0.f;
        h14[j] = ((hh + 55) % HH) * 14;               // rolled row offset, float4 units
    }

    // ---- prefetch x: 6 independent LDG.128 (overlaps the weight staging) ----
    const float4* __restrict__ x4 = (const float4*)x;
    float4 xv[2][3];
    #pragma unroll
    for (int ii = 0; ii < 2; ++ii) {
        const int c = 2 * (ig * 2 + ii) + o;
        const float4* xb = x4 + c * (HH * 14) + s4 + f4l;
        #pragma unroll
        for (int j = 0; j < 3; ++j)
            xv[ii][j] = __ldg(xb + h14[j]);
    }

    // ---- stage weights to smem, H-masks folded into w1 ----
    w1s[tid] = w1[tid] * msk[tid % 3];
    if (tid < 256) w1s[tid + 512] = w1[tid + 512] * msk[(tid + 2) % 3];
    else if (tid < 448) w2s[tid - 256] = w2[tid - 256];
    __syncthreads();

    // ---------------- Phase 1: 96 FMAs from registers ----------------
    float4 acc[4];
    #pragma unroll
    for (int k = 0; k < 4; ++k) acc[k] = make_float4(0.f, 0.f, 0.f, 0.f);

    #pragma unroll
    for (int ii = 0; ii < 2; ++ii) {
        const float* wb = w1s + (ig * 2 + ii) * 3;
        #pragma unroll
        for (int j = 0; j < 3; ++j) {
            const float4 v = xv[ii][j];
            #pragma unroll
            for (int k = 0; k < 4; ++k) {
                const float w = wb[k * 192 + j];
                acc[k].x = fmaf(w, v.x, acc[k].x);
                acc[k].y = fmaf(w, v.y, acc[k].y);
                acc[k].z = fmaf(w, v.z, acc[k].z);
                acc[k].w = fmaf(w, v.w, acc[k].w);
            }
        }
    }

    // ---- shfl pre-reduction: combine ig pairs (ig ^ 1), same o & f4l ----
    // go differs by 2 -> tid differs by 16 -> same warp
    #pragma unroll
    for (int k = 0; k < 4; ++k) {
        acc[k].x += __shfl_xor_sync(0xffffffffu, acc[k].x, 16);
        acc[k].y += __shfl_xor_sync(0xffffffffu, acc[k].y, 16);
        acc[k].z += __shfl_xor_sync(0xffffffffu, acc[k].z, 16);
        acc[k].w += __shfl_xor_sync(0xffffffffu, acc[k].w, 16);
    }
    if (((tid >> 4) & 1) == 0) {             // ig even: store pair sum
        const int gr = ig >> 1;              // reduced group 0..15
        float4* ps4 = (float4*)psum;
        #pragma unroll
        for (int k = 0; k < 4; ++k)
            ps4[((gr * 2 + o) * 4 + k) * NF4B + f4l] = acc[k];
    }
    __syncthreads();

    // ---- reduce 16 groups per (o,k,local col): 256 threads, one output each ----
    if (tid < 256) {
        const int ll = tid & 31;             // local col 0..31
        const int ok = tid >> 5;             // o*4 + k
        const int oo = ok >> 2;
        const int k  = ok & 3;
        float ssum = 0.f;
        #pragma unroll
        for (int g = 0; g < 16; ++g)
            ssum += psum[((g * 2 + oo) * 4 + k) * 32 + ll];
        inter_s[ok * 34 + ll + 1] = ssum;
        if (tid < 16)                        // zero halo at padded idx 0 and 33
            inter_s[(tid >> 1) * 34 + (tid & 1) * 33] = 0.f;
    }
    __syncthreads();

    // ---------------- Phase 2: float4 outputs, 896 quads, 2 per thread ----------------
    if (tid < 448) {
        float4* __restrict__ out4 = (float4*)out;
        #pragma unroll
        for (int t = 0; t < 2; ++t) {
            const int q   = tid + t * 448;   // 0..895
            const int f4o = q % 7;           // output quad within half-row
            const int co  = q / 7;           // 0..127 = i32*4 + k4
            const int i32 = co >> 2;
            const int k4  = co & 3;
            const int n0  = f4o * 4;         // local output col base

            const float* wb = w2s + i32 * 6;
            float4 a = make_float4(0.f, 0.f, 0.f, 0.f);
            #pragma unroll
            for (int oo = 0; oo < 2; ++oo) {
                const float* ib = inter_s + (oo * 4 + k4) * 34 + n0 + lshift;  // taps +0..+5
                const float s0 = ib[0], s1 = ib[1], s2 = ib[2],
                            s3 = ib[3], s4v = ib[4], s5 = ib[5];
                const float wA = wb[oo * 3 + 0];
                const float wB = wb[oo * 3 + 1];
                const float wC = wb[oo * 3 + 2];
                a.x = fmaf(wA, s0, fmaf(wB, s1, fmaf(wC, s2, a.x)));
                a.y = fmaf(wA, s1, fmaf(wB, s2, fmaf(wC, s3, a.y)));
                a.z = fmaf(wA, s2, fmaf(wB, s3, fmaf(wC, s4v, a.z)));
                a.w = fmaf(wA, s3, fmaf(wB, s4v, fmaf(wC, s5, a.w)));
            }
            out4[(co * (HH * WW) + m * WW + nb + n0) >> 2] = a;
        }
    }
}

extern "C" void kernel_launch(void* const* d_in, const int* in_sizes, int n_in,
                              void* d_out, int out_size)
{
    const float* x  = (const float*)d_in[0];   // (1,128,56,56)
    const float* w1 = (const float*)d_in[1];   // (4,64,3)
    const float* w2 = (const float*)d_in[2];   // (32,2,3)
    float* out = (float*)d_out;                // (1,128,56,56)

    dim3 grid(2, HH);                          // 112 blocks
    fused_shift_conv_v10<<<grid, THREADS>>>(x, w1, w2, out);
}